// round 15
// baseline (speedup 1.0000x reference)
#include <cuda_runtime.h>
#include <cuda_fp16.h>
#include <cuda_bf16.h>
#include <mma.h>
#include <cstdint>

using namespace nvcuda;

#define NN 100000
#define NE 1600000
#define HID 64
#define NEG_SLOPE 0.2f
#define CAP 64              // slots per node incl. self

// ---------------- scratch (device globals) ----------------
__device__ __half g_h[NN * HID];    // layer-1 pre-attention features (fp16, gather-only)
__device__ float  g_hl[NN * HID];   // layer-1 output (GEMM2 input, fp32)
__device__ __half g_h2[NN * HID];   // layer-2 pre-attention features (fp16)
__device__ float  g_as[NN];
__device__ float  g_ad[NN];
__device__ float  g_as2[NN];
__device__ float  g_ad2[NN];
__device__ int    g_cnt[NN];
__device__ int    g_slots[(size_t)NN * CAP];

// ---------------- f32x2 helpers ----------------
__device__ __forceinline__ unsigned long long ffma2(unsigned long long a,
                                                    unsigned long long b,
                                                    unsigned long long c) {
    unsigned long long d;
    asm("fma.rn.f32x2 %0,%1,%2,%3;" : "=l"(d) : "l"(a), "l"(b), "l"(c));
    return d;
}
__device__ __forceinline__ unsigned long long dup2(float x) {
    unsigned long long r;
    asm("mov.b64 %0,{%1,%1};" : "=l"(r) : "f"(x));
    return r;
}
__device__ __forceinline__ float2 unpk(unsigned long long p) {
    float2 r;
    asm("mov.b64 {%0,%1},%2;" : "=f"(r.x), "=f"(r.y) : "l"(p));
    return r;
}

// ================= adjacency build (slot-based; self-loop pre-seeded) =================
__global__ void zero_kernel() {
    int i = blockIdx.x * blockDim.x + threadIdx.x;
    if (i < NN) {
        g_cnt[i] = 1;                       // slot 0 = self loop
        g_slots[(size_t)i * CAP] = i;
    }
}
__global__ void fill_kernel(const int* __restrict__ ei) {
    int e = blockIdx.x * blockDim.x + threadIdx.x;
    if (e >= NE) return;
    int s = ei[e], d = ei[NE + e];
    int idx = atomicAdd(&g_cnt[d], 1);
    if (idx < CAP) g_slots[(size_t)d * CAP + idx] = s;
}

// ============ GEMM1 via WMMA bf16 split-precision (hh+hl+lh) + fused scores ============
// CTA tile 128x64; 8 warps, warp w owns rows [w*16, w*16+16); K=256 in 16-chunks.
#define PAD_HS 68
__global__ void __launch_bounds__(256) gemm1_wmma_kernel(const float* __restrict__ X,
                                                         const float* __restrict__ W,
                                                         const float* __restrict__ a_s,
                                                         const float* __restrict__ a_d,
                                                         __half* __restrict__ H,
                                                         float* __restrict__ as_out,
                                                         float* __restrict__ ad_out) {
    __shared__ __align__(16) union {
        struct {
            __nv_bfloat16 Ah[128][32];   // 16 cols used, stride 32 (16B-aligned rows)
            __nv_bfloat16 Al[128][32];
            __nv_bfloat16 Bh[16][64];
            __nv_bfloat16 Bl[16][64];
        } st;
        float hs[128][PAD_HS];           // epilogue result tile
    } sm;
    __shared__ float s_as[64], s_ad[64];

    int t = threadIdx.x, w = t >> 5;
    int rowblk = blockIdx.x * 128;
    if (t < 64) { s_as[t] = a_s[t]; s_ad[t] = a_d[t]; }

    wmma::fragment<wmma::accumulator, 16, 16, 16, float> acc[4];
    #pragma unroll
    for (int i = 0; i < 4; i++) wmma::fill_fragment(acc[i], 0.0f);

    // A staging map: thread -> (row, 8-col half); B: thread -> (k, 4-col group)
    int arow = t >> 1, acol8 = (t & 1) * 8;
    int grow = rowblk + arow; if (grow >= NN) grow = NN - 1;
    const float* xrow = X + (size_t)grow * 256;
    int bk = t >> 4, bc4 = (t & 15) * 4;

    for (int k0 = 0; k0 < 256; k0 += 16) {
        __syncthreads();   // prior-iteration fragment loads done before restaging
        // ---- stage A hi/lo ----
        float4 v0 = *(const float4*)(xrow + k0 + acol8);
        float4 v1 = *(const float4*)(xrow + k0 + acol8 + 4);
        float vf[8] = {v0.x, v0.y, v0.z, v0.w, v1.x, v1.y, v1.z, v1.w};
        __nv_bfloat16 hi8[8], lo8[8];
        #pragma unroll
        for (int i = 0; i < 8; i++) {
            hi8[i] = __float2bfloat16_rn(vf[i]);
            lo8[i] = __float2bfloat16_rn(vf[i] - __bfloat162float(hi8[i]));
        }
        *(uint4*)&sm.st.Ah[arow][acol8] = *(uint4*)hi8;
        *(uint4*)&sm.st.Al[arow][acol8] = *(uint4*)lo8;
        // ---- stage B hi/lo ----
        float4 wv = *(const float4*)(W + (size_t)(k0 + bk) * 64 + bc4);
        float wf[4] = {wv.x, wv.y, wv.z, wv.w};
        __nv_bfloat16 bh4[4], bl4[4];
        #pragma unroll
        for (int i = 0; i < 4; i++) {
            bh4[i] = __float2bfloat16_rn(wf[i]);
            bl4[i] = __float2bfloat16_rn(wf[i] - __bfloat162float(bh4[i]));
        }
        *(uint2*)&sm.st.Bh[bk][bc4] = *(uint2*)bh4;
        *(uint2*)&sm.st.Bl[bk][bc4] = *(uint2*)bl4;
        __syncthreads();

        wmma::fragment<wmma::matrix_a, 16, 16, 16, __nv_bfloat16, wmma::row_major> ah, al;
        wmma::load_matrix_sync(ah, &sm.st.Ah[w * 16][0], 32);
        wmma::load_matrix_sync(al, &sm.st.Al[w * 16][0], 32);
        #pragma unroll
        for (int nb = 0; nb < 4; nb++) {
            wmma::fragment<wmma::matrix_b, 16, 16, 16, __nv_bfloat16, wmma::row_major> bh, bl;
            wmma::load_matrix_sync(bh, &sm.st.Bh[0][nb * 16], 64);
            wmma::load_matrix_sync(bl, &sm.st.Bl[0][nb * 16], 64);
            wmma::mma_sync(acc[nb], ah, bh, acc[nb]);
            wmma::mma_sync(acc[nb], ah, bl, acc[nb]);
            wmma::mma_sync(acc[nb], al, bh, acc[nb]);
        }
    }
    __syncthreads();
    #pragma unroll
    for (int nb = 0; nb < 4; nb++)
        wmma::store_matrix_sync(&sm.hs[w * 16][nb * 16], acc[nb], PAD_HS, wmma::mem_row_major);
    __syncthreads();

    // ---- epilogue: 2 threads per row, 32 cols each ----
    int row = t >> 1, hf = t & 1;
    int gr = rowblk + row;
    const float* hsrow = &sm.hs[row][hf * 32];
    float ps = 0.0f, pd = 0.0f;
    __half hv[32];
    #pragma unroll
    for (int c = 0; c < 32; c++) {
        float f = hsrow[c];
        ps = fmaf(f, s_as[hf * 32 + c], ps);
        pd = fmaf(f, s_ad[hf * 32 + c], pd);
        hv[c] = __float2half_rn(f);
    }
    ps += __shfl_xor_sync(0xffffffffu, ps, 1);
    pd += __shfl_xor_sync(0xffffffffu, pd, 1);
    if (gr < NN) {
        uint4* dst = (uint4*)(H + (size_t)gr * 64 + hf * 32);
        #pragma unroll
        for (int i = 0; i < 4; i++) dst[i] = *(uint4*)&hv[i * 8];
        if (hf == 0) { as_out[gr] = ps; ad_out[gr] = pd; }
    }
}

// ============ tiled GEMM2 (128x64, FFMA2) + fused scores; fp16 H output ============
template<int K>
__global__ void __launch_bounds__(256) gemm_kernel(const float* __restrict__ X,
                                                   const float* __restrict__ W,
                                                   const float* __restrict__ a_s,
                                                   const float* __restrict__ a_d,
                                                   __half* __restrict__ H,
                                                   float* __restrict__ as_out,
                                                   float* __restrict__ ad_out) {
    __shared__ float xs[16][132];
    __shared__ float ws[16][64];
    int t = threadIdx.x;
    int rowblk = blockIdx.x * 128;

    int col4 = (t & 15) * 4;
    int r0   = (t >> 4) * 8;

    unsigned long long acc[4][4];
    #pragma unroll
    for (int i = 0; i < 4; i++)
        #pragma unroll
        for (int j = 0; j < 4; j++) acc[i][j] = 0ull;

    int lrow = t >> 1;
    int lk   = (t & 1) * 8;
    int grow = rowblk + lrow; if (grow >= NN) grow = NN - 1;
    const float4* xsrc = (const float4*)(X + (size_t)grow * K);

    for (int k0 = 0; k0 < K; k0 += 16) {
        float4 v0 = xsrc[(k0 + lk) >> 2];
        float4 v1 = xsrc[(k0 + lk + 4) >> 2];
        float4 wv4 = ((const float4*)(W + k0 * 64))[t];
        __syncthreads();
        xs[lk + 0][lrow] = v0.x; xs[lk + 1][lrow] = v0.y;
        xs[lk + 2][lrow] = v0.z; xs[lk + 3][lrow] = v0.w;
        xs[lk + 4][lrow] = v1.x; xs[lk + 5][lrow] = v1.y;
        xs[lk + 6][lrow] = v1.z; xs[lk + 7][lrow] = v1.w;
        ((float4*)ws)[t] = wv4;
        __syncthreads();
        #pragma unroll
        for (int kk = 0; kk < 16; kk++) {
            float4 wv = *(const float4*)&ws[kk][col4];
            unsigned long long wd0 = dup2(wv.x), wd1 = dup2(wv.y),
                               wd2 = dup2(wv.z), wd3 = dup2(wv.w);
            #pragma unroll
            for (int i = 0; i < 4; i++) {
                unsigned long long xp =
                    *(const unsigned long long*)&xs[kk][r0 + 2 * i];
                acc[i][0] = ffma2(xp, wd0, acc[i][0]);
                acc[i][1] = ffma2(xp, wd1, acc[i][1]);
                acc[i][2] = ffma2(xp, wd2, acc[i][2]);
                acc[i][3] = ffma2(xp, wd3, acc[i][3]);
            }
        }
    }

    int orow = rowblk + r0;
    float2 c[4][4];
    #pragma unroll
    for (int i = 0; i < 4; i++) {
        #pragma unroll
        for (int j = 0; j < 4; j++) c[i][j] = unpk(acc[i][j]);
        int rlo = orow + 2 * i, rhi = rlo + 1;
        if (rlo < NN) {
            union { __half2 h[2]; uint2 u; } pk;
            pk.h[0] = __floats2half2_rn(c[i][0].x, c[i][1].x);
            pk.h[1] = __floats2half2_rn(c[i][2].x, c[i][3].x);
            *(uint2*)(H + (size_t)rlo * 64 + col4) = pk.u;
        }
        if (rhi < NN) {
            union { __half2 h[2]; uint2 u; } pk;
            pk.h[0] = __floats2half2_rn(c[i][0].y, c[i][1].y);
            pk.h[1] = __floats2half2_rn(c[i][2].y, c[i][3].y);
            *(uint2*)(H + (size_t)rhi * 64 + col4) = pk.u;
        }
    }

    float4 asv = *(const float4*)(a_s + col4);
    float4 adv = *(const float4*)(a_d + col4);
    float ps[8], pd[8];
    #pragma unroll
    for (int i = 0; i < 4; i++) {
        ps[2*i]   = c[i][0].x*asv.x + c[i][1].x*asv.y + c[i][2].x*asv.z + c[i][3].x*asv.w;
        ps[2*i+1] = c[i][0].y*asv.x + c[i][1].y*asv.y + c[i][2].y*asv.z + c[i][3].y*asv.w;
        pd[2*i]   = c[i][0].x*adv.x + c[i][1].x*adv.y + c[i][2].x*adv.z + c[i][3].x*adv.w;
        pd[2*i+1] = c[i][0].y*adv.x + c[i][1].y*adv.y + c[i][2].y*adv.z + c[i][3].y*adv.w;
    }
    #pragma unroll
    for (int r = 0; r < 8; r++) {
        #pragma unroll
        for (int o = 8; o; o >>= 1) {
            ps[r] += __shfl_down_sync(0xffffffffu, ps[r], o, 16);
            pd[r] += __shfl_down_sync(0xffffffffu, pd[r], o, 16);
        }
    }
    if ((t & 15) == 0) {
        #pragma unroll
        for (int r = 0; r < 8; r++) {
            int row = orow + r;
            if (row < NN) { as_out[row] = ps[r]; ad_out[row] = pd[r]; }
        }
    }
}

// -------- cooperative softmax-weighted gather (fp16 features; self in slot 0) --------
__device__ __forceinline__ void gather_node(const __half* __restrict__ h,
                                            const float* __restrict__ as,
                                            const float* __restrict__ ad,
                                            int n, int lane,
                                            float& h0, float& h1) {
    int deg = g_cnt[n];
    if (deg > CAP) deg = CAP;
    const int* slots = g_slots + (size_t)n * CAP;
    int c0 = 2 * lane;
    float adn = ad[n];

    int   sA = 0, sB = 0;
    float wA = 0.0f, wB = 0.0f;
    if (lane < deg) {
        sA = slots[lane];
        float e = as[sA] + adn;
        wA = __expf((e > 0.0f) ? e : NEG_SLOPE * e);
    }
    if (lane + 32 < deg) {
        sB = slots[lane + 32];
        float e = as[sB] + adn;
        wB = __expf((e > 0.0f) ? e : NEG_SLOPE * e);
    }

    float den = wA + wB;
    #pragma unroll
    for (int o = 16; o; o >>= 1)
        den += __shfl_xor_sync(0xffffffffu, den, o);

    float accx = 0.0f, accy = 0.0f;

    int m1 = (deg < 32) ? deg : 32;
    int j = 0;
    for (; j + 4 <= m1; j += 4) {
        int t0 = __shfl_sync(0xffffffffu, sA, j);
        int t1 = __shfl_sync(0xffffffffu, sA, j + 1);
        int t2 = __shfl_sync(0xffffffffu, sA, j + 2);
        int t3 = __shfl_sync(0xffffffffu, sA, j + 3);
        float2 v0 = __half22float2(*(const __half2*)(h + (size_t)t0 * HID + c0));
        float2 v1 = __half22float2(*(const __half2*)(h + (size_t)t1 * HID + c0));
        float2 v2 = __half22float2(*(const __half2*)(h + (size_t)t2 * HID + c0));
        float2 v3 = __half22float2(*(const __half2*)(h + (size_t)t3 * HID + c0));
        float w0 = __shfl_sync(0xffffffffu, wA, j);
        float w1 = __shfl_sync(0xffffffffu, wA, j + 1);
        float w2 = __shfl_sync(0xffffffffu, wA, j + 2);
        float w3 = __shfl_sync(0xffffffffu, wA, j + 3);
        accx = fmaf(w0, v0.x, accx); accy = fmaf(w0, v0.y, accy);
        accx = fmaf(w1, v1.x, accx); accy = fmaf(w1, v1.y, accy);
        accx = fmaf(w2, v2.x, accx); accy = fmaf(w2, v2.y, accy);
        accx = fmaf(w3, v3.x, accx); accy = fmaf(w3, v3.y, accy);
    }
    for (; j < m1; j++) {
        int   s = __shfl_sync(0xffffffffu, sA, j);
        float w = __shfl_sync(0xffffffffu, wA, j);
        float2 v = __half22float2(*(const __half2*)(h + (size_t)s * HID + c0));
        accx = fmaf(w, v.x, accx); accy = fmaf(w, v.y, accy);
    }
    int m2 = deg - 32;
    j = 0;
    for (; j + 4 <= m2; j += 4) {
        int t0 = __shfl_sync(0xffffffffu, sB, j);
        int t1 = __shfl_sync(0xffffffffu, sB, j + 1);
        int t2 = __shfl_sync(0xffffffffu, sB, j + 2);
        int t3 = __shfl_sync(0xffffffffu, sB, j + 3);
        float2 v0 = __half22float2(*(const __half2*)(h + (size_t)t0 * HID + c0));
        float2 v1 = __half22float2(*(const __half2*)(h + (size_t)t1 * HID + c0));
        float2 v2 = __half22float2(*(const __half2*)(h + (size_t)t2 * HID + c0));
        float2 v3 = __half22float2(*(const __half2*)(h + (size_t)t3 * HID + c0));
        float w0 = __shfl_sync(0xffffffffu, wB, j);
        float w1 = __shfl_sync(0xffffffffu, wB, j + 1);
        float w2 = __shfl_sync(0xffffffffu, wB, j + 2);
        float w3 = __shfl_sync(0xffffffffu, wB, j + 3);
        accx = fmaf(w0, v0.x, accx); accy = fmaf(w0, v0.y, accy);
        accx = fmaf(w1, v1.x, accx); accy = fmaf(w1, v1.y, accy);
        accx = fmaf(w2, v2.x, accx); accy = fmaf(w2, v2.y, accy);
        accx = fmaf(w3, v3.x, accx); accy = fmaf(w3, v3.y, accy);
    }
    for (; j < m2; j++) {
        int   s = __shfl_sync(0xffffffffu, sB, j);
        float w = __shfl_sync(0xffffffffu, wB, j);
        float2 v = __half22float2(*(const __half2*)(h + (size_t)s * HID + c0));
        accx = fmaf(w, v.x, accx); accy = fmaf(w, v.y, accy);
    }

    float inv = 1.0f / den;
    h0 = accx * inv;
    h1 = accy * inv;
}

// ============ aggregate layer1 + bias + relu -> g_hl (fp32) ============
__global__ void __launch_bounds__(256) agg1_kernel(const __half* __restrict__ h,
                                                   const float* __restrict__ b1,
                                                   float* __restrict__ HL) {
    int n = (blockIdx.x * blockDim.x + threadIdx.x) >> 5;
    int lane = threadIdx.x & 31;
    if (n >= NN) return;
    int c0 = 2 * lane;

    float h0, h1;
    gather_node(h, g_as, g_ad, n, lane, h0, h1);
    h0 += b1[c0]; h1 += b1[c0 + 1];
    h0 = (h0 > 0.0f) ? h0 : 0.0f;
    h1 = (h1 > 0.0f) ? h1 : 0.0f;
    *(float2*)(HL + (size_t)n * HID + c0) = make_float2(h0, h1);
}

// ============ final: aggregate layer2 + bias + relu + both heads ============
__global__ void __launch_bounds__(256) agg2_heads_kernel(const __half* __restrict__ h,
                                                         const float* __restrict__ b2,
                                                         const float* __restrict__ Wf,
                                                         const float* __restrict__ bf,
                                                         const float* __restrict__ Ws,
                                                         const float* __restrict__ bs,
                                                         float* __restrict__ out) {
    int n = (blockIdx.x * blockDim.x + threadIdx.x) >> 5;
    int lane = threadIdx.x & 31;
    if (n >= NN) return;
    int c0 = 2 * lane;

    float h0, h1;
    gather_node(h, g_as2, g_ad2, n, lane, h0, h1);
    h0 += b2[c0]; h1 += b2[c0 + 1];
    h0 = (h0 > 0.0f) ? h0 : 0.0f;
    h1 = (h1 > 0.0f) ? h1 : 0.0f;

    float acc[10];
    #pragma unroll
    for (int j = 0; j < 3; j++)
        acc[j] = h0 * Wf[c0 * 3 + j] + h1 * Wf[(c0 + 1) * 3 + j];
    #pragma unroll
    for (int j = 0; j < 7; j++)
        acc[3 + j] = h0 * Ws[c0 * 7 + j] + h1 * Ws[(c0 + 1) * 7 + j];
    #pragma unroll
    for (int j = 0; j < 10; j++) {
        #pragma unroll
        for (int o = 16; o; o >>= 1)
            acc[j] += __shfl_down_sync(0xffffffffu, acc[j], o);
    }
    if (lane == 0) {
        #pragma unroll
        for (int j = 0; j < 3; j++) out[(size_t)n * 3 + j] = acc[j] + bf[j];
        #pragma unroll
        for (int j = 0; j < 7; j++)
            out[(size_t)NN * 3 + (size_t)n * 7 + j] = acc[3 + j] + bs[j];
    }
}

extern "C" void kernel_launch(void* const* d_in, const int* in_sizes, int n_in,
                              void* d_out, int out_size) {
    const float* x    = (const float*)d_in[0];
    const int*   ei   = (const int*)d_in[1];
    const float* W1   = (const float*)d_in[2];
    const float* as1  = (const float*)d_in[3];
    const float* ad1  = (const float*)d_in[4];
    const float* b1   = (const float*)d_in[5];
    const float* W2   = (const float*)d_in[6];
    const float* as2  = (const float*)d_in[7];
    const float* ad2  = (const float*)d_in[8];
    const float* b2   = (const float*)d_in[9];
    const float* Wf   = (const float*)d_in[10];
    const float* bf   = (const float*)d_in[11];
    const float* Ws   = (const float*)d_in[12];
    const float* bs   = (const float*)d_in[13];
    float* out = (float*)d_out;

    __half* d_gh;   cudaGetSymbolAddress((void**)&d_gh,   g_h);
    float*  d_ghl;  cudaGetSymbolAddress((void**)&d_ghl,  g_hl);
    __half* d_gh2;  cudaGetSymbolAddress((void**)&d_gh2,  g_h2);
    float*  d_gas;  cudaGetSymbolAddress((void**)&d_gas,  g_as);
    float*  d_gad;  cudaGetSymbolAddress((void**)&d_gad,  g_ad);
    float*  d_gas2; cudaGetSymbolAddress((void**)&d_gas2, g_as2);
    float*  d_gad2; cudaGetSymbolAddress((void**)&d_gad2, g_ad2);

    const int TB = 256;
    dim3 gNode((NN + TB - 1) / TB);
    dim3 gEdge((NE + TB - 1) / TB);
    dim3 gGemm((NN + 127) / 128);
    dim3 gWarpNode(((size_t)NN * 32 + TB - 1) / TB);

    // Fork side stream: adjacency build overlaps gemm1 (disjoint data).
    cudaStream_t s2;
    cudaEvent_t evFork, evJoin;
    cudaStreamCreateWithFlags(&s2, cudaStreamNonBlocking);
    cudaEventCreateWithFlags(&evFork, cudaEventDisableTiming);
    cudaEventCreateWithFlags(&evJoin, cudaEventDisableTiming);

    cudaEventRecord(evFork, 0);
    cudaStreamWaitEvent(s2, evFork, 0);

    zero_kernel<<<gNode, TB, 0, s2>>>();                           // launch 0
    fill_kernel<<<gEdge, TB, 0, s2>>>(ei);                         // launch 1

    // ---- layer-1 GEMM on tensor cores (WMMA bf16 split) ----
    gemm1_wmma_kernel<<<gGemm, 256>>>(x, W1, as1, ad1, d_gh, d_gas, d_gad);  // launch 2

    cudaEventRecord(evJoin, s2);
    cudaStreamWaitEvent(0, evJoin, 0);

    agg1_kernel<<<gWarpNode, TB>>>(d_gh, b1, d_ghl);               // launch 3 (profiled)
    gemm_kernel<64><<<gGemm, TB>>>(d_ghl, W2, as2, ad2, d_gh2, d_gas2, d_gad2);
    agg2_heads_kernel<<<gWarpNode, TB>>>(d_gh2, b2, Wf, bf, Ws, bs, out);
}

// round 16
// speedup vs baseline: 1.3563x; 1.3563x over previous
#include <cuda_runtime.h>
#include <cuda_fp16.h>
#include <cstdint>

#define NN 100000
#define NE 1600000
#define HID 64
#define NEG_SLOPE 0.2f
#define CAP 64              // slots per node incl. self

// ---------------- scratch (device globals) ----------------
__device__ __half g_h[NN * HID];    // layer-1 pre-attention features (fp16, gather-only)
__device__ float  g_hl[NN * HID];   // layer-1 output (GEMM2 input, fp32)
__device__ __half g_h2[NN * HID];   // layer-2 pre-attention features (fp16)
__device__ float  g_as[NN];
__device__ float  g_ad[NN];
__device__ float  g_as2[NN];
__device__ float  g_ad2[NN];
__device__ int    g_cnt[NN];
__device__ int    g_slots[(size_t)NN * CAP];

// ---------------- f32x2 helpers ----------------
__device__ __forceinline__ unsigned long long ffma2(unsigned long long a,
                                                    unsigned long long b,
                                                    unsigned long long c) {
    unsigned long long d;
    asm("fma.rn.f32x2 %0,%1,%2,%3;" : "=l"(d) : "l"(a), "l"(b), "l"(c));
    return d;
}
__device__ __forceinline__ unsigned long long dup2(float x) {
    unsigned long long r;
    asm("mov.b64 %0,{%1,%1};" : "=l"(r) : "f"(x));
    return r;
}
__device__ __forceinline__ float2 unpk(unsigned long long p) {
    float2 r;
    asm("mov.b64 {%0,%1},%2;" : "=f"(r.x), "=f"(r.y) : "l"(p));
    return r;
}

// ================= adjacency build (slot-based; self-loop pre-seeded) =================
__global__ void zero_kernel() {
    int i = blockIdx.x * blockDim.x + threadIdx.x;
    if (i < NN) {
        g_cnt[i] = 1;                       // slot 0 = self loop
        g_slots[(size_t)i * CAP] = i;
    }
}
__global__ void fill_kernel(const int* __restrict__ ei) {
    int e = blockIdx.x * blockDim.x + threadIdx.x;
    if (e >= NE) return;
    int s = ei[e], d = ei[NE + e];
    int idx = atomicAdd(&g_cnt[d], 1);
    if (idx < CAP) g_slots[(size_t)d * CAP + idx] = s;
}

// ====== tiled GEMM (128x64, FFMA2, double-buffered smem) + fused scores ======
template<int K>
__global__ void __launch_bounds__(256) gemm_kernel(const float* __restrict__ X,
                                                   const float* __restrict__ W,
                                                   const float* __restrict__ a_s,
                                                   const float* __restrict__ a_d,
                                                   __half* __restrict__ H,
                                                   float* __restrict__ as_out,
                                                   float* __restrict__ ad_out) {
    __shared__ float xs[2][16][132];   // transposed x chunk: xs[b][kk][row]
    __shared__ float ws[2][16][64];    // w chunk: ws[b][kk][col]
    int t = threadIdx.x;
    int rowblk = blockIdx.x * 128;

    int col4 = (t & 15) * 4;
    int r0   = (t >> 4) * 8;

    unsigned long long acc[4][4];
    #pragma unroll
    for (int i = 0; i < 4; i++)
        #pragma unroll
        for (int j = 0; j < 4; j++) acc[i][j] = 0ull;

    int lrow = t >> 1;
    int lk   = (t & 1) * 8;
    int grow = rowblk + lrow; if (grow >= NN) grow = NN - 1;
    const float4* xsrc = (const float4*)(X + (size_t)grow * K);

    const int NC = K / 16;

    // prologue: load + store chunk 0 into buffer 0
    float4 v0 = xsrc[lk >> 2];
    float4 v1 = xsrc[(lk + 4) >> 2];
    float4 wv4 = ((const float4*)W)[t];
    xs[0][lk + 0][lrow] = v0.x; xs[0][lk + 1][lrow] = v0.y;
    xs[0][lk + 2][lrow] = v0.z; xs[0][lk + 3][lrow] = v0.w;
    xs[0][lk + 4][lrow] = v1.x; xs[0][lk + 5][lrow] = v1.y;
    xs[0][lk + 6][lrow] = v1.z; xs[0][lk + 7][lrow] = v1.w;
    ((float4*)ws[0])[t] = wv4;
    __syncthreads();

    for (int c = 0; c < NC; c++) {
        int buf = c & 1;
        if (c + 1 < NC) {          // issue next chunk's global loads early
            int k0 = (c + 1) * 16;
            v0 = xsrc[(k0 + lk) >> 2];
            v1 = xsrc[(k0 + lk + 4) >> 2];
            wv4 = ((const float4*)(W + k0 * 64))[t];
        }
        #pragma unroll
        for (int kk = 0; kk < 16; kk++) {
            float4 wv = *(const float4*)&ws[buf][kk][col4];
            unsigned long long wd0 = dup2(wv.x), wd1 = dup2(wv.y),
                               wd2 = dup2(wv.z), wd3 = dup2(wv.w);
            #pragma unroll
            for (int i = 0; i < 4; i++) {
                unsigned long long xp =
                    *(const unsigned long long*)&xs[buf][kk][r0 + 2 * i];
                acc[i][0] = ffma2(xp, wd0, acc[i][0]);
                acc[i][1] = ffma2(xp, wd1, acc[i][1]);
                acc[i][2] = ffma2(xp, wd2, acc[i][2]);
                acc[i][3] = ffma2(xp, wd3, acc[i][3]);
            }
        }
        if (c + 1 < NC) {          // store into idle buffer; single barrier
            int nb = buf ^ 1;
            xs[nb][lk + 0][lrow] = v0.x; xs[nb][lk + 1][lrow] = v0.y;
            xs[nb][lk + 2][lrow] = v0.z; xs[nb][lk + 3][lrow] = v0.w;
            xs[nb][lk + 4][lrow] = v1.x; xs[nb][lk + 5][lrow] = v1.y;
            xs[nb][lk + 6][lrow] = v1.z; xs[nb][lk + 7][lrow] = v1.w;
            ((float4*)ws[nb])[t] = wv4;
            __syncthreads();
        }
    }

    int orow = rowblk + r0;
    float2 c2[4][4];
    #pragma unroll
    for (int i = 0; i < 4; i++) {
        #pragma unroll
        for (int j = 0; j < 4; j++) c2[i][j] = unpk(acc[i][j]);
        int rlo = orow + 2 * i, rhi = rlo + 1;
        if (rlo < NN) {
            union { __half2 h[2]; uint2 u; } pk;
            pk.h[0] = __floats2half2_rn(c2[i][0].x, c2[i][1].x);
            pk.h[1] = __floats2half2_rn(c2[i][2].x, c2[i][3].x);
            *(uint2*)(H + (size_t)rlo * 64 + col4) = pk.u;
        }
        if (rhi < NN) {
            union { __half2 h[2]; uint2 u; } pk;
            pk.h[0] = __floats2half2_rn(c2[i][0].y, c2[i][1].y);
            pk.h[1] = __floats2half2_rn(c2[i][2].y, c2[i][3].y);
            *(uint2*)(H + (size_t)rhi * 64 + col4) = pk.u;
        }
    }

    float4 asv = *(const float4*)(a_s + col4);
    float4 adv = *(const float4*)(a_d + col4);
    float ps[8], pd[8];
    #pragma unroll
    for (int i = 0; i < 4; i++) {
        ps[2*i]   = c2[i][0].x*asv.x + c2[i][1].x*asv.y + c2[i][2].x*asv.z + c2[i][3].x*asv.w;
        ps[2*i+1] = c2[i][0].y*asv.x + c2[i][1].y*asv.y + c2[i][2].y*asv.z + c2[i][3].y*asv.w;
        pd[2*i]   = c2[i][0].x*adv.x + c2[i][1].x*adv.y + c2[i][2].x*adv.z + c2[i][3].x*adv.w;
        pd[2*i+1] = c2[i][0].y*adv.x + c2[i][1].y*adv.y + c2[i][2].y*adv.z + c2[i][3].y*adv.w;
    }
    #pragma unroll
    for (int r = 0; r < 8; r++) {
        #pragma unroll
        for (int o = 8; o; o >>= 1) {
            ps[r] += __shfl_down_sync(0xffffffffu, ps[r], o, 16);
            pd[r] += __shfl_down_sync(0xffffffffu, pd[r], o, 16);
        }
    }
    if ((t & 15) == 0) {
        #pragma unroll
        for (int r = 0; r < 8; r++) {
            int row = orow + r;
            if (row < NN) { as_out[row] = ps[r]; ad_out[row] = pd[r]; }
        }
    }
}

// -------- cooperative softmax-weighted gather (fp16 features; self in slot 0) --------
__device__ __forceinline__ void gather_node(const __half* __restrict__ h,
                                            const float* __restrict__ as,
                                            const float* __restrict__ ad,
                                            int n, int lane,
                                            float& h0, float& h1) {
    int deg = g_cnt[n];
    if (deg > CAP) deg = CAP;
    const int* slots = g_slots + (size_t)n * CAP;
    int c0 = 2 * lane;
    float adn = ad[n];

    int   sA = 0, sB = 0;
    float wA = 0.0f, wB = 0.0f;
    if (lane < deg) {
        sA = slots[lane];
        float e = as[sA] + adn;
        wA = __expf((e > 0.0f) ? e : NEG_SLOPE * e);
    }
    if (lane + 32 < deg) {
        sB = slots[lane + 32];
        float e = as[sB] + adn;
        wB = __expf((e > 0.0f) ? e : NEG_SLOPE * e);
    }

    float den = wA + wB;
    #pragma unroll
    for (int o = 16; o; o >>= 1)
        den += __shfl_xor_sync(0xffffffffu, den, o);

    float accx = 0.0f, accy = 0.0f;

    int m1 = (deg < 32) ? deg : 32;
    int j = 0;
    for (; j + 4 <= m1; j += 4) {
        int t0 = __shfl_sync(0xffffffffu, sA, j);
        int t1 = __shfl_sync(0xffffffffu, sA, j + 1);
        int t2 = __shfl_sync(0xffffffffu, sA, j + 2);
        int t3 = __shfl_sync(0xffffffffu, sA, j + 3);
        float2 v0 = __half22float2(*(const __half2*)(h + (size_t)t0 * HID + c0));
        float2 v1 = __half22float2(*(const __half2*)(h + (size_t)t1 * HID + c0));
        float2 v2 = __half22float2(*(const __half2*)(h + (size_t)t2 * HID + c0));
        float2 v3 = __half22float2(*(const __half2*)(h + (size_t)t3 * HID + c0));
        float w0 = __shfl_sync(0xffffffffu, wA, j);
        float w1 = __shfl_sync(0xffffffffu, wA, j + 1);
        float w2 = __shfl_sync(0xffffffffu, wA, j + 2);
        float w3 = __shfl_sync(0xffffffffu, wA, j + 3);
        accx = fmaf(w0, v0.x, accx); accy = fmaf(w0, v0.y, accy);
        accx = fmaf(w1, v1.x, accx); accy = fmaf(w1, v1.y, accy);
        accx = fmaf(w2, v2.x, accx); accy = fmaf(w2, v2.y, accy);
        accx = fmaf(w3, v3.x, accx); accy = fmaf(w3, v3.y, accy);
    }
    for (; j < m1; j++) {
        int   s = __shfl_sync(0xffffffffu, sA, j);
        float w = __shfl_sync(0xffffffffu, wA, j);
        float2 v = __half22float2(*(const __half2*)(h + (size_t)s * HID + c0));
        accx = fmaf(w, v.x, accx); accy = fmaf(w, v.y, accy);
    }
    int m2 = deg - 32;
    j = 0;
    for (; j + 4 <= m2; j += 4) {
        int t0 = __shfl_sync(0xffffffffu, sB, j);
        int t1 = __shfl_sync(0xffffffffu, sB, j + 1);
        int t2 = __shfl_sync(0xffffffffu, sB, j + 2);
        int t3 = __shfl_sync(0xffffffffu, sB, j + 3);
        float2 v0 = __half22float2(*(const __half2*)(h + (size_t)t0 * HID + c0));
        float2 v1 = __half22float2(*(const __half2*)(h + (size_t)t1 * HID + c0));
        float2 v2 = __half22float2(*(const __half2*)(h + (size_t)t2 * HID + c0));
        float2 v3 = __half22float2(*(const __half2*)(h + (size_t)t3 * HID + c0));
        float w0 = __shfl_sync(0xffffffffu, wB, j);
        float w1 = __shfl_sync(0xffffffffu, wB, j + 1);
        float w2 = __shfl_sync(0xffffffffu, wB, j + 2);
        float w3 = __shfl_sync(0xffffffffu, wB, j + 3);
        accx = fmaf(w0, v0.x, accx); accy = fmaf(w0, v0.y, accy);
        accx = fmaf(w1, v1.x, accx); accy = fmaf(w1, v1.y, accy);
        accx = fmaf(w2, v2.x, accx); accy = fmaf(w2, v2.y, accy);
        accx = fmaf(w3, v3.x, accx); accy = fmaf(w3, v3.y, accy);
    }
    for (; j < m2; j++) {
        int   s = __shfl_sync(0xffffffffu, sB, j);
        float w = __shfl_sync(0xffffffffu, wB, j);
        float2 v = __half22float2(*(const __half2*)(h + (size_t)s * HID + c0));
        accx = fmaf(w, v.x, accx); accy = fmaf(w, v.y, accy);
    }

    float inv = 1.0f / den;
    h0 = accx * inv;
    h1 = accy * inv;
}

// ============ aggregate layer1 + bias + relu -> g_hl (fp32) ============
__global__ void __launch_bounds__(256) agg1_kernel(const __half* __restrict__ h,
                                                   const float* __restrict__ b1,
                                                   float* __restrict__ HL) {
    int n = (blockIdx.x * blockDim.x + threadIdx.x) >> 5;
    int lane = threadIdx.x & 31;
    if (n >= NN) return;
    int c0 = 2 * lane;

    float h0, h1;
    gather_node(h, g_as, g_ad, n, lane, h0, h1);
    h0 += b1[c0]; h1 += b1[c0 + 1];
    h0 = (h0 > 0.0f) ? h0 : 0.0f;
    h1 = (h1 > 0.0f) ? h1 : 0.0f;
    *(float2*)(HL + (size_t)n * HID + c0) = make_float2(h0, h1);
}

// ============ final: aggregate layer2 + bias + relu + both heads ============
__global__ void __launch_bounds__(256) agg2_heads_kernel(const __half* __restrict__ h,
                                                         const float* __restrict__ b2,
                                                         const float* __restrict__ Wf,
                                                         const float* __restrict__ bf,
                                                         const float* __restrict__ Ws,
                                                         const float* __restrict__ bs,
                                                         float* __restrict__ out) {
    int n = (blockIdx.x * blockDim.x + threadIdx.x) >> 5;
    int lane = threadIdx.x & 31;
    if (n >= NN) return;
    int c0 = 2 * lane;

    float h0, h1;
    gather_node(h, g_as2, g_ad2, n, lane, h0, h1);
    h0 += b2[c0]; h1 += b2[c0 + 1];
    h0 = (h0 > 0.0f) ? h0 : 0.0f;
    h1 = (h1 > 0.0f) ? h1 : 0.0f;

    float acc[10];
    #pragma unroll
    for (int j = 0; j < 3; j++)
        acc[j] = h0 * Wf[c0 * 3 + j] + h1 * Wf[(c0 + 1) * 3 + j];
    #pragma unroll
    for (int j = 0; j < 7; j++)
        acc[3 + j] = h0 * Ws[c0 * 7 + j] + h1 * Ws[(c0 + 1) * 7 + j];
    #pragma unroll
    for (int j = 0; j < 10; j++) {
        #pragma unroll
        for (int o = 16; o; o >>= 1)
            acc[j] += __shfl_down_sync(0xffffffffu, acc[j], o);
    }
    if (lane == 0) {
        #pragma unroll
        for (int j = 0; j < 3; j++) out[(size_t)n * 3 + j] = acc[j] + bf[j];
        #pragma unroll
        for (int j = 0; j < 7; j++)
            out[(size_t)NN * 3 + (size_t)n * 7 + j] = acc[3 + j] + bs[j];
    }
}

extern "C" void kernel_launch(void* const* d_in, const int* in_sizes, int n_in,
                              void* d_out, int out_size) {
    const float* x    = (const float*)d_in[0];
    const int*   ei   = (const int*)d_in[1];
    const float* W1   = (const float*)d_in[2];
    const float* as1  = (const float*)d_in[3];
    const float* ad1  = (const float*)d_in[4];
    const float* b1   = (const float*)d_in[5];
    const float* W2   = (const float*)d_in[6];
    const float* as2  = (const float*)d_in[7];
    const float* ad2  = (const float*)d_in[8];
    const float* b2   = (const float*)d_in[9];
    const float* Wf   = (const float*)d_in[10];
    const float* bf   = (const float*)d_in[11];
    const float* Ws   = (const float*)d_in[12];
    const float* bs   = (const float*)d_in[13];
    float* out = (float*)d_out;

    __half* d_gh;   cudaGetSymbolAddress((void**)&d_gh,   g_h);
    float*  d_ghl;  cudaGetSymbolAddress((void**)&d_ghl,  g_hl);
    __half* d_gh2;  cudaGetSymbolAddress((void**)&d_gh2,  g_h2);
    float*  d_gas;  cudaGetSymbolAddress((void**)&d_gas,  g_as);
    float*  d_gad;  cudaGetSymbolAddress((void**)&d_gad,  g_ad);
    float*  d_gas2; cudaGetSymbolAddress((void**)&d_gas2, g_as2);
    float*  d_gad2; cudaGetSymbolAddress((void**)&d_gad2, g_ad2);

    const int TB = 256;
    dim3 gNode((NN + TB - 1) / TB);
    dim3 gEdge((NE + TB - 1) / TB);
    dim3 gGemm((NN + 127) / 128);
    dim3 gWarpNode(((size_t)NN * 32 + TB - 1) / TB);

    // Fork side stream: adjacency build overlaps gemm1 (disjoint data).
    cudaStream_t s2;
    cudaEvent_t evFork, evJoin;
    cudaStreamCreateWithFlags(&s2, cudaStreamNonBlocking);
    cudaEventCreateWithFlags(&evFork, cudaEventDisableTiming);
    cudaEventCreateWithFlags(&evJoin, cudaEventDisableTiming);

    cudaEventRecord(evFork, 0);
    cudaStreamWaitEvent(s2, evFork, 0);

    zero_kernel<<<gNode, TB, 0, s2>>>();                           // launch 0
    fill_kernel<<<gEdge, TB, 0, s2>>>(ei);                         // launch 1

    // ---- layer-1 GEMM (FFMA2, double-buffered) ----
    gemm_kernel<256><<<gGemm, TB>>>(x, W1, as1, ad1, d_gh, d_gas, d_gad);  // launch 2

    cudaEventRecord(evJoin, s2);
    cudaStreamWaitEvent(0, evJoin, 0);

    agg1_kernel<<<gWarpNode, TB>>>(d_gh, b1, d_ghl);               // launch 3 (profiled)
    gemm_kernel<64><<<gGemm, TB>>>(d_ghl, W2, as2, ad2, d_gh2, d_gas2, d_gad2);
    agg2_heads_kernel<<<gWarpNode, TB>>>(d_gh2, b2, Wf, bf, Ws, bs, out);
}

// round 17
// speedup vs baseline: 1.3674x; 1.0082x over previous
#include <cuda_runtime.h>
#include <cuda_fp16.h>
#include <cstdint>

#define NN 100000
#define NE 1600000
#define HID 64
#define NEG_SLOPE 0.2f
#define CAP 64              // slots per node incl. self

// ---------------- scratch (device globals) ----------------
__device__ __half g_h[NN * HID];    // layer-1 pre-attention features (fp16, gather-only)
__device__ float  g_hl[NN * HID];   // layer-1 output (GEMM2 input, fp32)
__device__ __half g_h2[NN * HID];   // layer-2 pre-attention features (fp16)
__device__ float  g_as[NN];
__device__ float  g_ad[NN];
__device__ float  g_as2[NN];
__device__ float  g_ad2[NN];
__device__ int    g_cnt[NN];
__device__ int    g_slots[(size_t)NN * CAP];

// ---------------- f32x2 helpers ----------------
__device__ __forceinline__ unsigned long long ffma2(unsigned long long a,
                                                    unsigned long long b,
                                                    unsigned long long c) {
    unsigned long long d;
    asm("fma.rn.f32x2 %0,%1,%2,%3;" : "=l"(d) : "l"(a), "l"(b), "l"(c));
    return d;
}
__device__ __forceinline__ unsigned long long dup2(float x) {
    unsigned long long r;
    asm("mov.b64 %0,{%1,%1};" : "=l"(r) : "f"(x));
    return r;
}
__device__ __forceinline__ float2 unpk(unsigned long long p) {
    float2 r;
    asm("mov.b64 {%0,%1},%2;" : "=f"(r.x), "=f"(r.y) : "l"(p));
    return r;
}

// ================= adjacency build (slot-based; self-loop pre-seeded) =================
__global__ void zero_kernel() {
    int i = blockIdx.x * blockDim.x + threadIdx.x;
    if (i < NN) {
        g_cnt[i] = 1;                       // slot 0 = self loop
        g_slots[(size_t)i * CAP] = i;
    }
}
__global__ void fill_kernel(const int* __restrict__ ei) {
    int e = blockIdx.x * blockDim.x + threadIdx.x;
    if (e >= NE) return;
    int s = ei[e], d = ei[NE + e];
    int idx = atomicAdd(&g_cnt[d], 1);
    if (idx < CAP) g_slots[(size_t)d * CAP + idx] = s;
}

// ============ tiled GEMM (128x64, FFMA2, single-buffer R13) + fused scores ============
template<int K>
__global__ void __launch_bounds__(256) gemm_kernel(const float* __restrict__ X,
                                                   const float* __restrict__ W,
                                                   const float* __restrict__ a_s,
                                                   const float* __restrict__ a_d,
                                                   __half* __restrict__ H,
                                                   float* __restrict__ as_out,
                                                   float* __restrict__ ad_out) {
    __shared__ float xs[16][132];
    __shared__ float ws[16][64];
    int t = threadIdx.x;
    int rowblk = blockIdx.x * 128;

    int col4 = (t & 15) * 4;
    int r0   = (t >> 4) * 8;

    unsigned long long acc[4][4];
    #pragma unroll
    for (int i = 0; i < 4; i++)
        #pragma unroll
        for (int j = 0; j < 4; j++) acc[i][j] = 0ull;

    int lrow = t >> 1;
    int lk   = (t & 1) * 8;
    int grow = rowblk + lrow; if (grow >= NN) grow = NN - 1;
    const float4* xsrc = (const float4*)(X + (size_t)grow * K);

    for (int k0 = 0; k0 < K; k0 += 16) {
        float4 v0 = xsrc[(k0 + lk) >> 2];
        float4 v1 = xsrc[(k0 + lk + 4) >> 2];
        float4 wv4 = ((const float4*)(W + k0 * 64))[t];
        __syncthreads();
        xs[lk + 0][lrow] = v0.x; xs[lk + 1][lrow] = v0.y;
        xs[lk + 2][lrow] = v0.z; xs[lk + 3][lrow] = v0.w;
        xs[lk + 4][lrow] = v1.x; xs[lk + 5][lrow] = v1.y;
        xs[lk + 6][lrow] = v1.z; xs[lk + 7][lrow] = v1.w;
        ((float4*)ws)[t] = wv4;
        __syncthreads();
        #pragma unroll
        for (int kk = 0; kk < 16; kk++) {
            float4 wv = *(const float4*)&ws[kk][col4];
            unsigned long long wd0 = dup2(wv.x), wd1 = dup2(wv.y),
                               wd2 = dup2(wv.z), wd3 = dup2(wv.w);
            #pragma unroll
            for (int i = 0; i < 4; i++) {
                unsigned long long xp =
                    *(const unsigned long long*)&xs[kk][r0 + 2 * i];
                acc[i][0] = ffma2(xp, wd0, acc[i][0]);
                acc[i][1] = ffma2(xp, wd1, acc[i][1]);
                acc[i][2] = ffma2(xp, wd2, acc[i][2]);
                acc[i][3] = ffma2(xp, wd3, acc[i][3]);
            }
        }
    }

    int orow = rowblk + r0;
    float2 c[4][4];
    #pragma unroll
    for (int i = 0; i < 4; i++) {
        #pragma unroll
        for (int j = 0; j < 4; j++) c[i][j] = unpk(acc[i][j]);
        int rlo = orow + 2 * i, rhi = rlo + 1;
        if (rlo < NN) {
            union { __half2 h[2]; uint2 u; } pk;
            pk.h[0] = __floats2half2_rn(c[i][0].x, c[i][1].x);
            pk.h[1] = __floats2half2_rn(c[i][2].x, c[i][3].x);
            *(uint2*)(H + (size_t)rlo * 64 + col4) = pk.u;
        }
        if (rhi < NN) {
            union { __half2 h[2]; uint2 u; } pk;
            pk.h[0] = __floats2half2_rn(c[i][0].y, c[i][1].y);
            pk.h[1] = __floats2half2_rn(c[i][2].y, c[i][3].y);
            *(uint2*)(H + (size_t)rhi * 64 + col4) = pk.u;
        }
    }

    float4 asv = *(const float4*)(a_s + col4);
    float4 adv = *(const float4*)(a_d + col4);
    float ps[8], pd[8];
    #pragma unroll
    for (int i = 0; i < 4; i++) {
        ps[2*i]   = c[i][0].x*asv.x + c[i][1].x*asv.y + c[i][2].x*asv.z + c[i][3].x*asv.w;
        ps[2*i+1] = c[i][0].y*asv.x + c[i][1].y*asv.y + c[i][2].y*asv.z + c[i][3].y*asv.w;
        pd[2*i]   = c[i][0].x*adv.x + c[i][1].x*adv.y + c[i][2].x*adv.z + c[i][3].x*adv.w;
        pd[2*i+1] = c[i][0].y*adv.x + c[i][1].y*adv.y + c[i][2].y*adv.z + c[i][3].y*adv.w;
    }
    #pragma unroll
    for (int r = 0; r < 8; r++) {
        #pragma unroll
        for (int o = 8; o; o >>= 1) {
            ps[r] += __shfl_down_sync(0xffffffffu, ps[r], o, 16);
            pd[r] += __shfl_down_sync(0xffffffffu, pd[r], o, 16);
        }
    }
    if ((t & 15) == 0) {
        #pragma unroll
        for (int r = 0; r < 8; r++) {
            int row = orow + r;
            if (row < NN) { as_out[row] = ps[r]; ad_out[row] = pd[r]; }
        }
    }
}

// -------- cooperative gather: weights staged in smem (s,w) pairs, LDS.64 inner loop ----
// swp: per-warp staging array [CAP] of (src, bitcast w).
__device__ __forceinline__ void gather_node(const __half* __restrict__ h,
                                            const float* __restrict__ as,
                                            const float* __restrict__ ad,
                                            int n, int lane, uint2* swp,
                                            float& h0, float& h1) {
    int deg = g_cnt[n];
    if (deg > CAP) deg = CAP;
    const int* slots = g_slots + (size_t)n * CAP;
    int c0 = 2 * lane;
    float adn = ad[n];

    // lane-parallel weights, staged to smem
    float wA = 0.0f, wB = 0.0f;
    if (lane < deg) {
        int s = slots[lane];
        float e = as[s] + adn;
        wA = __expf((e > 0.0f) ? e : NEG_SLOPE * e);
        swp[lane] = make_uint2((unsigned)s, __float_as_uint(wA));
    }
    if (lane + 32 < deg) {
        int s = slots[lane + 32];
        float e = as[s] + adn;
        wB = __expf((e > 0.0f) ? e : NEG_SLOPE * e);
        swp[lane + 32] = make_uint2((unsigned)s, __float_as_uint(wB));
    }
    __syncwarp();

    float den = wA + wB;
    #pragma unroll
    for (int o = 16; o; o >>= 1)
        den += __shfl_xor_sync(0xffffffffu, den, o);

    float accx = 0.0f, accy = 0.0f;
    int j = 0;
    for (; j + 4 <= deg; j += 4) {
        uint2 p0 = swp[j], p1 = swp[j + 1], p2 = swp[j + 2], p3 = swp[j + 3];
        float2 v0 = __half22float2(*(const __half2*)(h + (size_t)p0.x * HID + c0));
        float2 v1 = __half22float2(*(const __half2*)(h + (size_t)p1.x * HID + c0));
        float2 v2 = __half22float2(*(const __half2*)(h + (size_t)p2.x * HID + c0));
        float2 v3 = __half22float2(*(const __half2*)(h + (size_t)p3.x * HID + c0));
        float w0 = __uint_as_float(p0.y), w1 = __uint_as_float(p1.y);
        float w2 = __uint_as_float(p2.y), w3 = __uint_as_float(p3.y);
        accx = fmaf(w0, v0.x, accx); accy = fmaf(w0, v0.y, accy);
        accx = fmaf(w1, v1.x, accx); accy = fmaf(w1, v1.y, accy);
        accx = fmaf(w2, v2.x, accx); accy = fmaf(w2, v2.y, accy);
        accx = fmaf(w3, v3.x, accx); accy = fmaf(w3, v3.y, accy);
    }
    for (; j < deg; j++) {
        uint2 p = swp[j];
        float w = __uint_as_float(p.y);
        float2 v = __half22float2(*(const __half2*)(h + (size_t)p.x * HID + c0));
        accx = fmaf(w, v.x, accx); accy = fmaf(w, v.y, accy);
    }

    float inv = 1.0f / den;
    h0 = accx * inv;
    h1 = accy * inv;
}

// ============ aggregate layer1 + bias + relu -> g_hl (fp32) ============
__global__ void __launch_bounds__(256) agg1_kernel(const __half* __restrict__ h,
                                                   const float* __restrict__ b1,
                                                   float* __restrict__ HL) {
    __shared__ uint2 swbuf[8][CAP];
    int n = (blockIdx.x * blockDim.x + threadIdx.x) >> 5;
    int lane = threadIdx.x & 31;
    int wid = (threadIdx.x >> 5) & 7;
    if (n >= NN) return;
    int c0 = 2 * lane;

    float h0, h1;
    gather_node(h, g_as, g_ad, n, lane, swbuf[wid], h0, h1);
    h0 += b1[c0]; h1 += b1[c0 + 1];
    h0 = (h0 > 0.0f) ? h0 : 0.0f;
    h1 = (h1 > 0.0f) ? h1 : 0.0f;
    *(float2*)(HL + (size_t)n * HID + c0) = make_float2(h0, h1);
}

// ============ final: aggregate layer2 + bias + relu + both heads ============
__global__ void __launch_bounds__(256) agg2_heads_kernel(const __half* __restrict__ h,
                                                         const float* __restrict__ b2,
                                                         const float* __restrict__ Wf,
                                                         const float* __restrict__ bf,
                                                         const float* __restrict__ Ws,
                                                         const float* __restrict__ bs,
                                                         float* __restrict__ out) {
    __shared__ uint2 swbuf[8][CAP];
    int n = (blockIdx.x * blockDim.x + threadIdx.x) >> 5;
    int lane = threadIdx.x & 31;
    int wid = (threadIdx.x >> 5) & 7;
    if (n >= NN) return;
    int c0 = 2 * lane;

    float h0, h1;
    gather_node(h, g_as2, g_ad2, n, lane, swbuf[wid], h0, h1);
    h0 += b2[c0]; h1 += b2[c0 + 1];
    h0 = (h0 > 0.0f) ? h0 : 0.0f;
    h1 = (h1 > 0.0f) ? h1 : 0.0f;

    float acc[10];
    #pragma unroll
    for (int j = 0; j < 3; j++)
        acc[j] = h0 * Wf[c0 * 3 + j] + h1 * Wf[(c0 + 1) * 3 + j];
    #pragma unroll
    for (int j = 0; j < 7; j++)
        acc[3 + j] = h0 * Ws[c0 * 7 + j] + h1 * Ws[(c0 + 1) * 7 + j];
    #pragma unroll
    for (int j = 0; j < 10; j++) {
        #pragma unroll
        for (int o = 16; o; o >>= 1)
            acc[j] += __shfl_down_sync(0xffffffffu, acc[j], o);
    }
    if (lane == 0) {
        #pragma unroll
        for (int j = 0; j < 3; j++) out[(size_t)n * 3 + j] = acc[j] + bf[j];
        #pragma unroll
        for (int j = 0; j < 7; j++)
            out[(size_t)NN * 3 + (size_t)n * 7 + j] = acc[3 + j] + bs[j];
    }
}

extern "C" void kernel_launch(void* const* d_in, const int* in_sizes, int n_in,
                              void* d_out, int out_size) {
    const float* x    = (const float*)d_in[0];
    const int*   ei   = (const int*)d_in[1];
    const float* W1   = (const float*)d_in[2];
    const float* as1  = (const float*)d_in[3];
    const float* ad1  = (const float*)d_in[4];
    const float* b1   = (const float*)d_in[5];
    const float* W2   = (const float*)d_in[6];
    const float* as2  = (const float*)d_in[7];
    const float* ad2  = (const float*)d_in[8];
    const float* b2   = (const float*)d_in[9];
    const float* Wf   = (const float*)d_in[10];
    const float* bf   = (const float*)d_in[11];
    const float* Ws   = (const float*)d_in[12];
    const float* bs   = (const float*)d_in[13];
    float* out = (float*)d_out;

    __half* d_gh;   cudaGetSymbolAddress((void**)&d_gh,   g_h);
    float*  d_ghl;  cudaGetSymbolAddress((void**)&d_ghl,  g_hl);
    __half* d_gh2;  cudaGetSymbolAddress((void**)&d_gh2,  g_h2);
    float*  d_gas;  cudaGetSymbolAddress((void**)&d_gas,  g_as);
    float*  d_gad;  cudaGetSymbolAddress((void**)&d_gad,  g_ad);
    float*  d_gas2; cudaGetSymbolAddress((void**)&d_gas2, g_as2);
    float*  d_gad2; cudaGetSymbolAddress((void**)&d_gad2, g_ad2);

    const int TB = 256;
    dim3 gNode((NN + TB - 1) / TB);
    dim3 gEdge((NE + TB - 1) / TB);
    dim3 gGemm((NN + 127) / 128);
    dim3 gWarpNode(((size_t)NN * 32 + TB - 1) / TB);

    // Fork side stream: adjacency build overlaps gemm1 (disjoint data).
    cudaStream_t s2;
    cudaEvent_t evFork, evJoin;
    cudaStreamCreateWithFlags(&s2, cudaStreamNonBlocking);
    cudaEventCreateWithFlags(&evFork, cudaEventDisableTiming);
    cudaEventCreateWithFlags(&evJoin, cudaEventDisableTiming);

    cudaEventRecord(evFork, 0);
    cudaStreamWaitEvent(s2, evFork, 0);

    zero_kernel<<<gNode, TB, 0, s2>>>();                           // launch 0
    fill_kernel<<<gEdge, TB, 0, s2>>>(ei);                         // launch 1

    // ---- layer-1 GEMM (FFMA2, single-buffer) ----
    gemm_kernel<256><<<gGemm, TB>>>(x, W1, as1, ad1, d_gh, d_gas, d_gad);  // launch 2

    cudaEventRecord(evJoin, s2);
    cudaStreamWaitEvent(0, evJoin, 0);

    agg1_kernel<<<gWarpNode, TB>>>(d_gh, b1, d_ghl);               // launch 3 (profiled)
    gemm_kernel<64><<<gGemm, TB>>>(d_ghl, W2, as2, ad2, d_gh2, d_gas2, d_gad2);
    agg2_heads_kernel<<<gWarpNode, TB>>>(d_gh2, b2, Wf, bf, Ws, bs, out);
}